// round 14
// baseline (speedup 1.0000x reference)
#include <cuda_runtime.h>
#include <cuda_fp16.h>
#include <math.h>
#include <stdint.h>

// Problem constants
#define LL   2048
#define HH   24
#define DD   128
#define HID  3072
#define MLPD 12288
#define NN1  21504   // 3*HID + MLP
#define NN2  15360   // HID + MLP
#define QKV  9216    // 3*HID
#define QK2  6144    // 2*HID
#define EPSF 1e-6f
#define LOG2E 1.4426950408889634f
#define MSPLIT 4                // mod_gemv k-split
// gemm2 decomposition: mlp K-part split 3 (4096 each), attn K-part split 2 (1536 each)
#define MLP_SLICE 4096
#define ATT_SLICE 1536

// ---------------- scratch (static device arrays; no allocs) ----------------
__device__ float g_mod[3 * HID];
__device__ float g_modp[MSPLIT][3 * HID];
__device__ __half g_xf[(size_t)LL * HID];              // x_mod fp16
__device__ __half g_w1f[(size_t)HID * NN1];            // w1 fp16 [K][N]
__device__ __half g_hqk[(size_t)LL * QK2];             // gemm1 q|k out fp16
__device__ __half g_qf[(size_t)HH * LL * DD];          // q (pre-scaled by D^-0.5)
__device__ __half g_kf[(size_t)HH * LL * DD];
__device__ __half g_vf[(size_t)HH * LL * DD];          // v fp16 [h][l][d]
__device__ __half g_ocf[(size_t)LL * NN2];             // attn | gelu(mlp) fp16
__device__ __half g_w2f[(size_t)NN2 * HID];            // w2 fp16 [K][N]
__device__ float  g_part[(size_t)5 * LL * HID];        // 3 mlp + 2 attn partials

// ---------------- helpers ----------------
__device__ __forceinline__ uint32_t smem_u32(const void* p) {
    uint32_t a;
    asm("{ .reg .u64 t; cvta.to.shared.u64 t, %1; cvt.u32.u64 %0, t; }" : "=r"(a) : "l"(p));
    return a;
}
__device__ __forceinline__ void cpasync16(uint32_t dst, const void* src) {
    asm volatile("cp.async.cg.shared.global [%0], [%1], 16;" :: "r"(dst), "l"(src));
}
__device__ __forceinline__ void cp_commit() { asm volatile("cp.async.commit_group;"); }
__device__ __forceinline__ void cp_wait1()  { asm volatile("cp.async.wait_group 1;" ::: "memory"); }
__device__ __forceinline__ void cp_wait0()  { asm volatile("cp.async.wait_group 0;" ::: "memory"); }

__device__ __forceinline__ void ldsm4(uint32_t& r0, uint32_t& r1, uint32_t& r2, uint32_t& r3, uint32_t a) {
    asm volatile("ldmatrix.sync.aligned.m8n8.x4.shared.b16 {%0,%1,%2,%3}, [%4];"
                 : "=r"(r0), "=r"(r1), "=r"(r2), "=r"(r3) : "r"(a));
}
__device__ __forceinline__ void ldsm4t(uint32_t& r0, uint32_t& r1, uint32_t& r2, uint32_t& r3, uint32_t a) {
    asm volatile("ldmatrix.sync.aligned.m8n8.x4.trans.shared.b16 {%0,%1,%2,%3}, [%4];"
                 : "=r"(r0), "=r"(r1), "=r"(r2), "=r"(r3) : "r"(a));
}
__device__ __forceinline__ void mma16816(float* c, const uint32_t* a, uint32_t b0, uint32_t b1) {
    asm volatile(
        "mma.sync.aligned.m16n8k16.row.col.f32.f16.f16.f32 "
        "{%0,%1,%2,%3},{%4,%5,%6,%7},{%8,%9},{%0,%1,%2,%3};\n"
        : "+f"(c[0]), "+f"(c[1]), "+f"(c[2]), "+f"(c[3])
        : "r"(a[0]), "r"(a[1]), "r"(a[2]), "r"(a[3]), "r"(b0), "r"(b1));
}
__device__ __forceinline__ float gelu_f(float v) {
    float c = 0.7978845608028654f * (v + 0.044715f * v * v * v);
    return 0.5f * v * (1.f + tanhf(c));
}

// ---------------- fp16 HMMA GEMM ----------------
// A [M][K] row-major fp16; B [K][N] (k-major) fp16 via ldmatrix.trans.
// CTA tile 256(m) x 128(n), 512 threads = 16 warps (4m x 4n, warp tile 64x32).
// K-chunk 128, double-buffered cp.async, swizzled smem.
// EPI: 0 plain fp32 | 6 gemm1 mixed: n<QK2 -> +bias fp16 Hqk; [QK2,QKV) -> +bias fp16 V; >=QKV -> gelu(+bias) fp16 C2
template<int EPI>
__global__ void __launch_bounds__(512, 1) hgemm(
    const __half* __restrict__ A, size_t lda, long sA,
    const __half* __restrict__ B, size_t ldb, long sB,
    float* __restrict__ C, size_t ldc, long sC, int K,
    const float* __restrict__ bias,
    __half* __restrict__ C2, size_t ldc2,
    __half* __restrict__ V, __half* __restrict__ Hqk)
{
    extern __shared__ char smem[];
    constexpr int TILEA = 256 * 256;     // 64 KB
    constexpr int TILEB = 128 * 256;     // 32 KB
    constexpr int STAGE = TILEA + TILEB; // 96 KB
    const uint32_t sb = smem_u32(smem);
    const int tid = threadIdx.x, wid = tid >> 5, lane = tid & 31;
    const int wm = wid & 3, wn = wid >> 2;    // 4m x 4n

    A += (long)blockIdx.z * sA;
    B += (long)blockIdx.z * sB;
    C += (long)blockIdx.z * sC;

    const size_t row0 = (size_t)blockIdx.x * 256;
    const size_t col0 = (size_t)blockIdx.y * 128;
    const __half* baseA = A + row0 * lda;
    const __half* baseB = B + col0;          // [K][N]: advance rows by k

    auto load_stage = [&](int s) {
        const uint32_t st = sb + (uint32_t)(s & 1) * STAGE;
        const int ko = s * 128;
        #pragma unroll
        for (int j = 0; j < 8; j++) {
            int c = tid + j * 512;
            int row = c >> 4, seg = c & 15;
            uint32_t dst = st + row * 256 + ((seg ^ (row & 7)) << 4);
            cpasync16(dst, (const char*)(baseA + ko + (size_t)row * lda) + seg * 16);
        }
        #pragma unroll
        for (int j = 0; j < 4; j++) {
            int c = tid + j * 512;
            int row = c >> 4, seg = c & 15;
            uint32_t dst = st + TILEA + row * 256 + ((seg ^ (row & 7)) << 4);
            cpasync16(dst, (const char*)(baseB + (size_t)(ko + row) * ldb) + seg * 16);
        }
    };

    float acc[4][4][4] = {};
    const int S = K >> 7;

    load_stage(0); cp_commit();
    for (int s = 0; s < S; s++) {
        cp_wait0();
        __syncthreads();
        if (s + 1 < S) { load_stage(s + 1); cp_commit(); }

        const uint32_t st = sb + (uint32_t)(s & 1) * STAGE;
        const uint32_t tA = st, tB = st + TILEA;

        #pragma unroll
        for (int kg = 0; kg < 8; kg++) {
            uint32_t af[4][4];
            {
                int arow = wm * 64 + (lane & 15);
                int ak8 = kg * 2 + (lane >> 4);
                #pragma unroll
                for (int im = 0; im < 4; im++) {
                    int r = arow + im * 16;
                    uint32_t off = r * 256 + ((ak8 ^ (r & 7)) << 4);
                    ldsm4(af[im][0], af[im][1], af[im][2], af[im][3], tA + off);
                }
            }
            int brow = kg * 16 + (lane & 7) + (lane & 8);
            #pragma unroll
            for (int g = 0; g < 2; g++) {
                int seg = wn * 4 + g * 2 + (lane >> 4);
                uint32_t off = brow * 256 + ((seg ^ (brow & 7)) << 4);
                uint32_t b0, b1, b2, b3;
                ldsm4t(b0, b1, b2, b3, tB + off);
                #pragma unroll
                for (int im = 0; im < 4; im++) {
                    mma16816(acc[im][2 * g],     af[im], b0, b1);
                    mma16816(acc[im][2 * g + 1], af[im], b2, b3);
                }
            }
        }
    }

    const int mode = (EPI == 6) ? ((col0 >= QKV) ? 2 : (col0 >= QK2 ? 1 : 0)) : 3;
    #pragma unroll
    for (int im = 0; im < 4; im++) {
        #pragma unroll
        for (int in = 0; in < 4; in++) {
            size_t m0 = row0 + wm * 64 + im * 16 + (lane >> 2);
            size_t n  = col0 + wn * 32 + in * 8 + (lane & 3) * 2;
            #pragma unroll
            for (int half = 0; half < 2; half++) {
                size_t m = m0 + half * 8;
                float v0 = acc[im][in][half * 2 + 0];
                float v1 = acc[im][in][half * 2 + 1];
                if (mode == 3) {
                    *(float2*)&C[m * ldc + n] = make_float2(v0, v1);
                } else if (mode == 0) {
                    v0 += bias[n]; v1 += bias[n + 1];
                    *(__half2*)&Hqk[m * QK2 + n] = __floats2half2_rn(v0, v1);
                } else if (mode == 1) {
                    v0 += bias[n]; v1 += bias[n + 1];
                    size_t head = (n - QK2) >> 7, d = (n - QK2) & 127;
                    *(__half2*)&V[(head * LL + m) * DD + d] = __floats2half2_rn(v0, v1);
                } else {
                    v0 += bias[n]; v1 += bias[n + 1];
                    __half2 h = __floats2half2_rn(gelu_f(v0), gelu_f(v1));
                    *(__half2*)&C2[m * ldc2 + (n - QK2)] = h;
                }
            }
        }
    }
}

// ---------------- reduce: out = x + gate*(sum of 5 partials + b2) ----------------
__global__ void reduce_out(const float* __restrict__ x, const float* __restrict__ b2,
                           float* __restrict__ out) {
    size_t i = ((size_t)blockIdx.x * 256 + threadIdx.x) * 4;
    int n = (int)(i % HID);
    const size_t STR = (size_t)LL * HID;
    float4 p0 = *(const float4*)&g_part[i];
    float4 p1 = *(const float4*)&g_part[STR + i];
    float4 p2 = *(const float4*)&g_part[2 * STR + i];
    float4 p3 = *(const float4*)&g_part[3 * STR + i];
    float4 p4 = *(const float4*)&g_part[4 * STR + i];
    float4 xb = *(const float4*)&x[i];
    float4 bb = *(const float4*)&b2[n];
    float4 gg = *(const float4*)&g_mod[2 * HID + n];
    float4 o;
    o.x = xb.x + gg.x * (p0.x + p1.x + p2.x + p3.x + p4.x + bb.x);
    o.y = xb.y + gg.y * (p0.y + p1.y + p2.y + p3.y + p4.y + bb.y);
    o.z = xb.z + gg.z * (p0.z + p1.z + p2.z + p3.z + p4.z + bb.z);
    o.w = xb.w + gg.w * (p0.w + p1.w + p2.w + p3.w + p4.w + bb.w);
    *(float4*)&out[i] = o;
}

// ---------------- fused flash attention ----------------
__global__ void __launch_bounds__(256, 1) flash_attn(
    const __half* __restrict__ Qg, const __half* __restrict__ Kg,
    const __half* __restrict__ Vg, __half* __restrict__ O)
{
    extern __shared__ char smem[];
    const uint32_t sb = smem_u32(smem);
    const int tid = threadIdx.x, wid = tid >> 5, lane = tid & 31;
    const int qb = blockIdx.x, head = blockIdx.y;
    constexpr uint32_t KOFF = 32768, VOFF = 98304;

    const __half* Qh = Qg + ((size_t)head * LL + (size_t)qb * 128) * DD;
    const __half* Kh = Kg + (size_t)head * LL * DD;
    const __half* Vh = Vg + (size_t)head * LL * DD;

    auto load_tile = [&](uint32_t dst, const __half* g) {
        #pragma unroll
        for (int i = 0; i < 8; i++) {
            int c = tid + i * 256;
            int row = c >> 4, ds = c & 15;
            uint32_t off = (uint32_t)(ds >> 3) * 16384 + row * 128 + (((ds & 7) ^ (row & 7)) << 4);
            cpasync16(dst + off, (const char*)g + (size_t)row * 256 + ds * 16);
        }
    };

    load_tile(sb, Qh); cp_commit();
    load_tile(sb + KOFF, Kh); load_tile(sb + VOFF, Vh); cp_commit();
    cp_wait1();
    __syncthreads();

    uint32_t qfr[8][4];
    {
        int r = wid * 16 + (lane & 15);
        #pragma unroll
        for (int ks = 0; ks < 8; ks++) {
            int seg = (ks & 3) * 2 + (lane >> 4);
            uint32_t addr = sb + (uint32_t)(ks >> 2) * 16384 + r * 128 + ((seg ^ (r & 7)) << 4);
            ldsm4(qfr[ks][0], qfr[ks][1], qfr[ks][2], qfr[ks][3], addr);
        }
    }

    float oacc[16][4] = {};
    float m0 = -1e30f, m1 = -1e30f, l0 = 0.f, l1 = 0.f;

    for (int j = 0; j < 16; j++) {
        const int buf = j & 1;
        if (j + 1 < 16) {
            load_tile(sb + KOFF + (buf ^ 1) * 32768, Kh + (size_t)(j + 1) * 128 * DD);
            load_tile(sb + VOFF + (buf ^ 1) * 32768, Vh + (size_t)(j + 1) * 128 * DD);
            cp_commit(); cp_wait1();
        } else cp_wait0();
        __syncthreads();

        float sacc[16][4] = {};
        const uint32_t tK = sb + KOFF + buf * 32768;
        #pragma unroll
        for (int ks = 0; ks < 8; ks++) {
            #pragma unroll
            for (int g = 0; g < 8; g++) {
                int r = g * 16 + (lane & 7) + ((lane >> 4) << 3);
                int seg = (ks & 3) * 2 + ((lane >> 3) & 1);
                uint32_t addr = tK + (uint32_t)(ks >> 2) * 16384 + r * 128 + ((seg ^ (r & 7)) << 4);
                uint32_t b0, b1, b2, b3;
                ldsm4(b0, b1, b2, b3, addr);
                mma16816(sacc[2 * g],     qfr[ks], b0, b1);
                mma16816(sacc[2 * g + 1], qfr[ks], b2, b3);
            }
        }

        float tm0 = -1e30f, tm1 = -1e30f;
        #pragma unroll
        for (int t = 0; t < 16; t++) {
            tm0 = fmaxf(tm0, fmaxf(sacc[t][0], sacc[t][1]));
            tm1 = fmaxf(tm1, fmaxf(sacc[t][2], sacc[t][3]));
        }
        tm0 = fmaxf(tm0, __shfl_xor_sync(~0u, tm0, 1));
        tm0 = fmaxf(tm0, __shfl_xor_sync(~0u, tm0, 2));
        tm1 = fmaxf(tm1, __shfl_xor_sync(~0u, tm1, 1));
        tm1 = fmaxf(tm1, __shfl_xor_sync(~0u, tm1, 2));
        float nm0 = fmaxf(m0, tm0), nm1 = fmaxf(m1, tm1);
        float f0 = exp2f((m0 - nm0) * LOG2E), f1 = exp2f((m1 - nm1) * LOG2E);
        m0 = nm0; m1 = nm1;

        uint32_t pP[8][4];
        float rs0 = 0.f, rs1 = 0.f;
        #pragma unroll
        for (int t = 0; t < 8; t++) {
            float p00 = exp2f((sacc[2*t][0]   - nm0) * LOG2E);
            float p01 = exp2f((sacc[2*t][1]   - nm0) * LOG2E);
            float p02 = exp2f((sacc[2*t][2]   - nm1) * LOG2E);
            float p03 = exp2f((sacc[2*t][3]   - nm1) * LOG2E);
            float p10 = exp2f((sacc[2*t+1][0] - nm0) * LOG2E);
            float p11 = exp2f((sacc[2*t+1][1] - nm0) * LOG2E);
            float p12 = exp2f((sacc[2*t+1][2] - nm1) * LOG2E);
            float p13 = exp2f((sacc[2*t+1][3] - nm1) * LOG2E);
            rs0 += p00 + p01 + p10 + p11;
            rs1 += p02 + p03 + p12 + p13;
            __half2 h;
            h = __floats2half2_rn(p00, p01); pP[t][0] = *(uint32_t*)&h;
            h = __floats2half2_rn(p02, p03); pP[t][1] = *(uint32_t*)&h;
            h = __floats2half2_rn(p10, p11); pP[t][2] = *(uint32_t*)&h;
            h = __floats2half2_rn(p12, p13); pP[t][3] = *(uint32_t*)&h;
        }
        rs0 += __shfl_xor_sync(~0u, rs0, 1); rs0 += __shfl_xor_sync(~0u, rs0, 2);
        rs1 += __shfl_xor_sync(~0u, rs1, 1); rs1 += __shfl_xor_sync(~0u, rs1, 2);
        l0 = l0 * f0 + rs0; l1 = l1 * f1 + rs1;
        #pragma unroll
        for (int t = 0; t < 16; t++) {
            oacc[t][0] *= f0; oacc[t][1] *= f0;
            oacc[t][2] *= f1; oacc[t][3] *= f1;
        }

        const uint32_t tV = sb + VOFF + buf * 32768;
        #pragma unroll
        for (int t = 0; t < 8; t++) {
            #pragma unroll
            for (int g = 0; g < 8; g++) {
                int r = t * 16 + (lane & 7) + (lane & 8);
                int seg = (g & 3) * 2 + (lane >> 4);
                uint32_t addr = tV + (uint32_t)(g >> 2) * 16384 + r * 128 + ((seg ^ (r & 7)) << 4);
                uint32_t b0, b1, b2, b3;
                ldsm4t(b0, b1, b2, b3, addr);
                mma16816(oacc[2 * g],     pP[t], b0, b1);
                mma16816(oacc[2 * g + 1], pP[t], b2, b3);
            }
        }
        __syncthreads();
    }

    float inv0 = 1.f / l0, inv1 = 1.f / l1;
    size_t m = (size_t)qb * 128 + wid * 16 + (lane >> 2);
    size_t col0 = (size_t)head * 128 + (lane & 3) * 2;
    #pragma unroll
    for (int t = 0; t < 16; t++) {
        __half2 h0 = __floats2half2_rn(oacc[t][0] * inv0, oacc[t][1] * inv0);
        __half2 h1 = __floats2half2_rn(oacc[t][2] * inv1, oacc[t][3] * inv1);
        *(__half2*)&O[m * NN2 + col0 + t * 8]       = h0;
        *(__half2*)&O[(m + 8) * NN2 + col0 + t * 8] = h1;
    }
}

// ---------------- vectorized fp32 -> fp16 cast (same layout) ----------------
__global__ void cast_half(const float* __restrict__ in, __half* __restrict__ o, size_t n8) {
    size_t i = (size_t)blockIdx.x * 256 + threadIdx.x;
    if (i >= n8) return;
    float4 a = *(const float4*)&in[i * 8];
    float4 b = *(const float4*)&in[i * 8 + 4];
    __half2 h[4] = { __floats2half2_rn(a.x, a.y), __floats2half2_rn(a.z, a.w),
                     __floats2half2_rn(b.x, b.y), __floats2half2_rn(b.z, b.w) };
    *(uint2*)&o[i * 8]     = make_uint2(*(uint32_t*)&h[0], *(uint32_t*)&h[1]);
    *(uint2*)&o[i * 8 + 4] = make_uint2(*(uint32_t*)&h[2], *(uint32_t*)&h[3]);
}

// ---------------- mod = silu(vec) @ mod_w + mod_b  (k-split partials) ----------------
__global__ void mod_gemv(const float* __restrict__ vec,
                         const float* __restrict__ mod_w) {
    __shared__ float sv[HID / MSPLIT];
    int tid = threadIdx.x;
    int ks = blockIdx.y;
    int k0 = ks * (HID / MSPLIT);
    for (int i = tid; i < HID / MSPLIT; i += blockDim.x) {
        float a = vec[k0 + i];
        sv[i] = a / (1.f + __expf(-a));
    }
    __syncthreads();
    int j = blockIdx.x * blockDim.x + tid;
    float acc = 0.f;
    #pragma unroll 4
    for (int k = 0; k < HID / MSPLIT; k++)
        acc += sv[k] * mod_w[(size_t)(k0 + k) * (3 * HID) + j];
    g_modp[ks][j] = acc;
}
__global__ void mod_reduce(const float* __restrict__ mod_b) {
    int j = blockIdx.x * 256 + threadIdx.x;
    float s = mod_b[j];
    #pragma unroll
    for (int k = 0; k < MSPLIT; k++) s += g_modp[k][j];
    g_mod[j] = s;
}

// ---------------- layernorm + modulation -> fp16 ----------------
__global__ void ln_mod_kernel(const float* __restrict__ x,
                              const float* __restrict__ gamma,
                              const float* __restrict__ beta) {
    __shared__ float red[32];
    int l = blockIdx.x;
    const float* xr = x + (size_t)l * HID;
    float s = 0.f, s2 = 0.f;
    for (int i = threadIdx.x; i < HID; i += 256) {
        float v = xr[i];
        s += v; s2 += v * v;
    }
    int lane = threadIdx.x & 31, wid = threadIdx.x >> 5;
    #pragma unroll
    for (int o = 16; o; o >>= 1) { s += __shfl_down_sync(~0u, s, o); s2 += __shfl_down_sync(~0u, s2, o); }
    if (lane == 0) { red[wid] = s; red[wid + 8] = s2; }
    __syncthreads();
    float ts = 0.f, ts2 = 0.f;
    if (threadIdx.x < 8) { ts = red[threadIdx.x]; ts2 = red[threadIdx.x + 8]; }
    #pragma unroll
    for (int o = 4; o; o >>= 1) { ts += __shfl_down_sync(0xff, ts, o); ts2 += __shfl_down_sync(0xff, ts2, o); }
    if (threadIdx.x == 0) { red[0] = ts; red[1] = ts2; }
    __syncthreads();
    float mu = red[0] / HID;
    float var = red[1] / HID - mu * mu;
    float rsig = rsqrtf(var + EPSF);
    for (int i = threadIdx.x; i < HID; i += 256) {
        float lnv = (xr[i] - mu) * rsig * gamma[i] + beta[i];
        float v = (1.f + g_mod[HID + i]) * lnv + g_mod[i];
        g_xf[(size_t)l * HID + i] = __float2half_rn(v);
    }
}

// ---------------- rmsnorm + rope (q,k) -> fp16 [h][l][d] ----------------
__global__ void qkv_prep(const float* __restrict__ pe,
                         const float* __restrict__ q_scale,
                         const float* __restrict__ k_scale) {
    int l = blockIdx.x, hd = blockIdx.y, which = blockIdx.z;
    size_t base = (size_t)l * QK2 + (size_t)which * HID + (size_t)hd * DD;
    int d = threadIdx.x;
    float t = __half2float(g_hqk[base + d]);
    size_t oi = ((size_t)hd * LL + l) * DD + d;
    const float* sc = which ? k_scale : q_scale;
    __shared__ float red[4];
    float v = t * t;
    #pragma unroll
    for (int o = 16; o; o >>= 1) v += __shfl_down_sync(~0u, v, o);
    if ((d & 31) == 0) red[d >> 5] = v;
    __syncthreads();
    float ss = red[0] + red[1] + red[2] + red[3];
    float r = rsqrtf(ss / DD + EPSF);
    __shared__ float s[DD];
    s[d] = t * r * sc[d];
    __syncthreads();
    int i = d >> 1, j = d & 1;
    const float* p = pe + (((size_t)l * (DD / 2) + i) * 2 + j) * 2;
    float out = p[0] * s[2 * i] + p[1] * s[2 * i + 1];
    if (which == 0) out *= 0.08838834764831845f;   // fold D^-0.5 into q
    if (which) g_kf[oi] = __float2half_rn(out);
    else       g_qf[oi] = __float2half_rn(out);
}

// ---------------- launcher ----------------
extern "C" void kernel_launch(void* const* d_in, const int* in_sizes, int n_in,
                              void* d_out, int out_size) {
    const float* x       = (const float*)d_in[0];
    const float* vec     = (const float*)d_in[1];
    const float* pe      = (const float*)d_in[2];
    const float* mod_w   = (const float*)d_in[3];
    const float* mod_b   = (const float*)d_in[4];
    const float* gamma   = (const float*)d_in[5];
    const float* beta    = (const float*)d_in[6];
    const float* w1      = (const float*)d_in[7];
    const float* b1      = (const float*)d_in[8];
    const float* q_scale = (const float*)d_in[9];
    const float* k_scale = (const float*)d_in[10];
    const float* w2      = (const float*)d_in[11];
    const float* b2      = (const float*)d_in[12];
    float* out = (float*)d_out;

    float *p_part;
    __half *p_xf, *p_w1f, *p_hq, *p_qf, *p_kf, *p_vf, *p_ocf, *p_w2f;
    cudaGetSymbolAddress((void**)&p_part, g_part);
    cudaGetSymbolAddress((void**)&p_xf, g_xf);
    cudaGetSymbolAddress((void**)&p_w1f, g_w1f);
    cudaGetSymbolAddress((void**)&p_hq, g_hqk);
    cudaGetSymbolAddress((void**)&p_qf, g_qf);
    cudaGetSymbolAddress((void**)&p_kf, g_kf);
    cudaGetSymbolAddress((void**)&p_vf, g_vf);
    cudaGetSymbolAddress((void**)&p_ocf, g_ocf);
    cudaGetSymbolAddress((void**)&p_w2f, g_w2f);

    const int SMEM = 2 * (256 + 128) * 256;   // 196608
    const int FSMEM = 163840;
    cudaFuncSetAttribute((const void*)hgemm<0>, cudaFuncAttributeMaxDynamicSharedMemorySize, SMEM);
    cudaFuncSetAttribute((const void*)hgemm<6>, cudaFuncAttributeMaxDynamicSharedMemorySize, SMEM);
    cudaFuncSetAttribute((const void*)flash_attn, cudaFuncAttributeMaxDynamicSharedMemorySize, FSMEM);

    // lazy-init side stream + events (handles only; captured graph identical every call)
    static cudaStream_t s1 = nullptr;
    static cudaEvent_t e_fork = nullptr, e_w1 = nullptr, e_g1 = nullptr, e_mlp = nullptr;
    if (!s1) {
        cudaStreamCreate(&s1);
        cudaEventCreateWithFlags(&e_fork, cudaEventDisableTiming);
        cudaEventCreateWithFlags(&e_w1, cudaEventDisableTiming);
        cudaEventCreateWithFlags(&e_g1, cudaEventDisableTiming);
        cudaEventCreateWithFlags(&e_mlp, cudaEventDisableTiming);
    }
    const size_t STR = (size_t)LL * HID;

    // fork side stream into capture
    cudaEventRecord(e_fork, 0);
    cudaStreamWaitEvent(s1, e_fork, 0);

    // side stream: weight casts (w1 then w2)
    cast_half<<<(unsigned)(((size_t)HID * NN1 / 8 + 255) / 256), 256, 0, s1>>>(w1, p_w1f, (size_t)HID * NN1 / 8);
    cudaEventRecord(e_w1, s1);
    cast_half<<<(unsigned)(((size_t)NN2 * HID / 8 + 255) / 256), 256, 0, s1>>>(w2, p_w2f, (size_t)NN2 * HID / 8);

    // main stream: mod chain
    mod_gemv<<<dim3((3 * HID) / 256, MSPLIT), 256>>>(vec, mod_w);
    mod_reduce<<<(3 * HID) / 256, 256>>>(mod_b);
    ln_mod_kernel<<<LL, 256>>>(x, gamma, beta);

    cudaStreamWaitEvent(0, e_w1, 0);
    // gemm1: q,k -> fp16 g_hqk; v -> g_vf; mlp -> gelu -> g_ocf (all fused)
    hgemm<6><<<dim3(LL / 256, NN1 / 128, 1), 512, SMEM>>>(
        p_xf, HID, 0, p_w1f, NN1, 0,
        nullptr, 0, 0, HID, b1, p_ocf, NN2, p_vf, p_hq);
    cudaEventRecord(e_g1, 0);

    // side stream: mlp part of gemm2 (K in [HID, NN2), split-3) — depends only on gemm1.
    // Reads oc cols [HID, NN2); concurrent flash writes cols [0, HID): disjoint.
    cudaStreamWaitEvent(s1, e_g1, 0);
    hgemm<0><<<dim3(LL / 256, HID / 128, 3), 512, SMEM, s1>>>(
        p_ocf + HID, NN2, MLP_SLICE, p_w2f + (size_t)HID * HID, HID, (long)MLP_SLICE * HID,
        p_part, HID, (long)STR, MLP_SLICE, nullptr, nullptr, 0, nullptr, nullptr);
    cudaEventRecord(e_mlp, s1);

    // main stream: attention path (concurrent with mlp gemm)
    qkv_prep<<<dim3(LL, HH, 2), 128>>>(pe, q_scale, k_scale);
    flash_attn<<<dim3(LL / 128, HH), 256, FSMEM>>>(p_qf, p_kf, p_vf, p_ocf);

    // main stream: attn part of gemm2 (K in [0, HID), split-2)
    hgemm<0><<<dim3(LL / 256, HID / 128, 2), 512, SMEM>>>(
        p_ocf, NN2, ATT_SLICE, p_w2f, HID, (long)ATT_SLICE * HID,
        p_part + 3 * STR, HID, (long)STR, ATT_SLICE, nullptr, nullptr, 0, nullptr, nullptr);

    // join: reduce all 5 partials
    cudaStreamWaitEvent(0, e_mlp, 0);
    reduce_out<<<(unsigned)((STR / 4) / 256), 256>>>(x, b2, out);
}

// round 15
// speedup vs baseline: 1.0350x; 1.0350x over previous
#include <cuda_runtime.h>
#include <cuda_fp16.h>
#include <math.h>
#include <stdint.h>

// Problem constants
#define LL   2048
#define HH   24
#define DD   128
#define HID  3072
#define MLPD 12288
#define NN1  21504   // 3*HID + MLP
#define NN2  15360   // HID + MLP
#define QKV  9216    // 3*HID
#define QK2  6144    // 2*HID
#define EPSF 1e-6f
#define LOG2E 1.4426950408889634f
#define KSPLIT 3
#define KCHUNK (NN2 / KSPLIT)   // 5120
#define MSPLIT 4                // mod_gemv k-split

// ---------------- scratch (static device arrays; no allocs) ----------------
__device__ float g_modp[MSPLIT][3 * HID];
__device__ __half g_xf[(size_t)LL * HID];              // x_mod fp16
__device__ __half g_w1f[(size_t)HID * NN1];            // w1 fp16 [K][N]
__device__ __half g_hqk[(size_t)LL * QK2];             // gemm1 q|k out fp16
__device__ __half g_qf[(size_t)HH * LL * DD];          // q (pre-scaled by D^-0.5)
__device__ __half g_kf[(size_t)HH * LL * DD];
__device__ __half g_vf[(size_t)HH * LL * DD];          // v fp16 [h][l][d]
__device__ __half g_ocf[(size_t)LL * NN2];             // attn | gelu(mlp) fp16
__device__ __half g_w2f[(size_t)NN2 * HID];            // w2 fp16 [K][N]
__device__ float  g_part[(size_t)KSPLIT * LL * HID];   // split-K partials

// ---------------- helpers ----------------
__device__ __forceinline__ uint32_t smem_u32(const void* p) {
    uint32_t a;
    asm("{ .reg .u64 t; cvta.to.shared.u64 t, %1; cvt.u32.u64 %0, t; }" : "=r"(a) : "l"(p));
    return a;
}
__device__ __forceinline__ void cpasync16(uint32_t dst, const void* src) {
    asm volatile("cp.async.cg.shared.global [%0], [%1], 16;" :: "r"(dst), "l"(src));
}
__device__ __forceinline__ void cp_commit() { asm volatile("cp.async.commit_group;"); }
__device__ __forceinline__ void cp_wait1()  { asm volatile("cp.async.wait_group 1;" ::: "memory"); }
__device__ __forceinline__ void cp_wait0()  { asm volatile("cp.async.wait_group 0;" ::: "memory"); }

__device__ __forceinline__ void ldsm4(uint32_t& r0, uint32_t& r1, uint32_t& r2, uint32_t& r3, uint32_t a) {
    asm volatile("ldmatrix.sync.aligned.m8n8.x4.shared.b16 {%0,%1,%2,%3}, [%4];"
                 : "=r"(r0), "=r"(r1), "=r"(r2), "=r"(r3) : "r"(a));
}
__device__ __forceinline__ void ldsm4t(uint32_t& r0, uint32_t& r1, uint32_t& r2, uint32_t& r3, uint32_t a) {
    asm volatile("ldmatrix.sync.aligned.m8n8.x4.trans.shared.b16 {%0,%1,%2,%3}, [%4];"
                 : "=r"(r0), "=r"(r1), "=r"(r2), "=r"(r3) : "r"(a));
}
__device__ __forceinline__ void mma16816(float* c, const uint32_t* a, uint32_t b0, uint32_t b1) {
    asm volatile(
        "mma.sync.aligned.m16n8k16.row.col.f32.f16.f16.f32 "
        "{%0,%1,%2,%3},{%4,%5,%6,%7},{%8,%9},{%0,%1,%2,%3};\n"
        : "+f"(c[0]), "+f"(c[1]), "+f"(c[2]), "+f"(c[3])
        : "r"(a[0]), "r"(a[1]), "r"(a[2]), "r"(a[3]), "r"(b0), "r"(b1));
}
__device__ __forceinline__ float gelu_f(float v) {
    float c = 0.7978845608028654f * (v + 0.044715f * v * v * v);
    return 0.5f * v * (1.f + tanhf(c));
}

// ---------------- fp16 HMMA GEMM ----------------
// A [M][K] row-major fp16; B [K][N] (k-major) fp16 via ldmatrix.trans.
// CTA tile 256(m) x 128(n), 512 threads = 16 warps (4m x 4n, warp tile 64x32).
// K-chunk 128, double-buffered cp.async, swizzled smem.
// EPI: 0 plain fp32 | 6 gemm1 mixed: n<QK2 -> +bias fp16 Hqk; [QK2,QKV) -> +bias fp16 V; >=QKV -> gelu(+bias) fp16 C2
template<int EPI>
__global__ void __launch_bounds__(512, 1) hgemm(
    const __half* __restrict__ A, size_t lda, long sA,
    const __half* __restrict__ B, size_t ldb, long sB,
    float* __restrict__ C, size_t ldc, long sC, int K,
    const float* __restrict__ bias,
    __half* __restrict__ C2, size_t ldc2,
    __half* __restrict__ V, __half* __restrict__ Hqk)
{
    extern __shared__ char smem[];
    constexpr int TILEA = 256 * 256;     // 64 KB
    constexpr int TILEB = 128 * 256;     // 32 KB
    constexpr int STAGE = TILEA + TILEB; // 96 KB
    const uint32_t sb = smem_u32(smem);
    const int tid = threadIdx.x, wid = tid >> 5, lane = tid & 31;
    const int wm = wid & 3, wn = wid >> 2;    // 4m x 4n

    A += (long)blockIdx.z * sA;
    B += (long)blockIdx.z * sB;
    C += (long)blockIdx.z * sC;

    const size_t row0 = (size_t)blockIdx.x * 256;
    const size_t col0 = (size_t)blockIdx.y * 128;
    const __half* baseA = A + row0 * lda;
    const __half* baseB = B + col0;          // [K][N]: advance rows by k

    auto load_stage = [&](int s) {
        const uint32_t st = sb + (uint32_t)(s & 1) * STAGE;
        const int ko = s * 128;
        #pragma unroll
        for (int j = 0; j < 8; j++) {
            int c = tid + j * 512;
            int row = c >> 4, seg = c & 15;
            uint32_t dst = st + row * 256 + ((seg ^ (row & 7)) << 4);
            cpasync16(dst, (const char*)(baseA + ko + (size_t)row * lda) + seg * 16);
        }
        #pragma unroll
        for (int j = 0; j < 4; j++) {
            int c = tid + j * 512;
            int row = c >> 4, seg = c & 15;
            uint32_t dst = st + TILEA + row * 256 + ((seg ^ (row & 7)) << 4);
            cpasync16(dst, (const char*)(baseB + (size_t)(ko + row) * ldb) + seg * 16);
        }
    };

    float acc[4][4][4] = {};
    const int S = K >> 7;

    load_stage(0); cp_commit();
    for (int s = 0; s < S; s++) {
        cp_wait0();
        __syncthreads();
        if (s + 1 < S) { load_stage(s + 1); cp_commit(); }

        const uint32_t st = sb + (uint32_t)(s & 1) * STAGE;
        const uint32_t tA = st, tB = st + TILEA;

        #pragma unroll
        for (int kg = 0; kg < 8; kg++) {
            uint32_t af[4][4];
            {
                int arow = wm * 64 + (lane & 15);
                int ak8 = kg * 2 + (lane >> 4);
                #pragma unroll
                for (int im = 0; im < 4; im++) {
                    int r = arow + im * 16;
                    uint32_t off = r * 256 + ((ak8 ^ (r & 7)) << 4);
                    ldsm4(af[im][0], af[im][1], af[im][2], af[im][3], tA + off);
                }
            }
            int brow = kg * 16 + (lane & 7) + (lane & 8);
            #pragma unroll
            for (int g = 0; g < 2; g++) {
                int seg = wn * 4 + g * 2 + (lane >> 4);
                uint32_t off = brow * 256 + ((seg ^ (brow & 7)) << 4);
                uint32_t b0, b1, b2, b3;
                ldsm4t(b0, b1, b2, b3, tB + off);
                #pragma unroll
                for (int im = 0; im < 4; im++) {
                    mma16816(acc[im][2 * g],     af[im], b0, b1);
                    mma16816(acc[im][2 * g + 1], af[im], b2, b3);
                }
            }
        }
    }

    const int mode = (EPI == 6) ? ((col0 >= QKV) ? 2 : (col0 >= QK2 ? 1 : 0)) : 3;
    #pragma unroll
    for (int im = 0; im < 4; im++) {
        #pragma unroll
        for (int in = 0; in < 4; in++) {
            size_t m0 = row0 + wm * 64 + im * 16 + (lane >> 2);
            size_t n  = col0 + wn * 32 + in * 8 + (lane & 3) * 2;
            #pragma unroll
            for (int half = 0; half < 2; half++) {
                size_t m = m0 + half * 8;
                float v0 = acc[im][in][half * 2 + 0];
                float v1 = acc[im][in][half * 2 + 1];
                if (mode == 3) {
                    *(float2*)&C[m * ldc + n] = make_float2(v0, v1);
                } else if (mode == 0) {
                    v0 += bias[n]; v1 += bias[n + 1];
                    *(__half2*)&Hqk[m * QK2 + n] = __floats2half2_rn(v0, v1);
                } else if (mode == 1) {
                    v0 += bias[n]; v1 += bias[n + 1];
                    size_t head = (n - QK2) >> 7, d = (n - QK2) & 127;
                    *(__half2*)&V[(head * LL + m) * DD + d] = __floats2half2_rn(v0, v1);
                } else {
                    v0 += bias[n]; v1 += bias[n + 1];
                    __half2 h = __floats2half2_rn(gelu_f(v0), gelu_f(v1));
                    *(__half2*)&C2[m * ldc2 + (n - QK2)] = h;
                }
            }
        }
    }
}

// ---------------- split-K reduce: out = x + gate*(p0+p1+p2+b2); gate folded from partials ----------------
__global__ void reduce_out(const float* __restrict__ x, const float* __restrict__ b2,
                           const float* __restrict__ mod_b, float* __restrict__ out) {
    size_t i = ((size_t)blockIdx.x * 256 + threadIdx.x) * 4;
    int n = (int)(i % HID);
    const size_t STR = (size_t)LL * HID;
    float4 p0 = *(const float4*)&g_part[i];
    float4 p1 = *(const float4*)&g_part[STR + i];
    float4 p2 = *(const float4*)&g_part[2 * STR + i];
    float4 xb = *(const float4*)&x[i];
    float4 bb = *(const float4*)&b2[n];
    float4 gg = *(const float4*)&mod_b[2 * HID + n];
    #pragma unroll
    for (int k = 0; k < MSPLIT; k++) {
        float4 gp = *(const float4*)&g_modp[k][2 * HID + n];
        gg.x += gp.x; gg.y += gp.y; gg.z += gp.z; gg.w += gp.w;
    }
    float4 o;
    o.x = xb.x + gg.x * (p0.x + p1.x + p2.x + bb.x);
    o.y = xb.y + gg.y * (p0.y + p1.y + p2.y + bb.y);
    o.z = xb.z + gg.z * (p0.z + p1.z + p2.z + bb.z);
    o.w = xb.w + gg.w * (p0.w + p1.w + p2.w + bb.w);
    *(float4*)&out[i] = o;
}

// ---------------- fused flash attention ----------------
__global__ void __launch_bounds__(256, 1) flash_attn(
    const __half* __restrict__ Qg, const __half* __restrict__ Kg,
    const __half* __restrict__ Vg, __half* __restrict__ O)
{
    extern __shared__ char smem[];
    const uint32_t sb = smem_u32(smem);
    const int tid = threadIdx.x, wid = tid >> 5, lane = tid & 31;
    const int qb = blockIdx.x, head = blockIdx.y;
    constexpr uint32_t KOFF = 32768, VOFF = 98304;

    const __half* Qh = Qg + ((size_t)head * LL + (size_t)qb * 128) * DD;
    const __half* Kh = Kg + (size_t)head * LL * DD;
    const __half* Vh = Vg + (size_t)head * LL * DD;

    auto load_tile = [&](uint32_t dst, const __half* g) {
        #pragma unroll
        for (int i = 0; i < 8; i++) {
            int c = tid + i * 256;
            int row = c >> 4, ds = c & 15;
            uint32_t off = (uint32_t)(ds >> 3) * 16384 + row * 128 + (((ds & 7) ^ (row & 7)) << 4);
            cpasync16(dst + off, (const char*)g + (size_t)row * 256 + ds * 16);
        }
    };

    load_tile(sb, Qh); cp_commit();
    load_tile(sb + KOFF, Kh); load_tile(sb + VOFF, Vh); cp_commit();
    cp_wait1();
    __syncthreads();

    uint32_t qfr[8][4];
    {
        int r = wid * 16 + (lane & 15);
        #pragma unroll
        for (int ks = 0; ks < 8; ks++) {
            int seg = (ks & 3) * 2 + (lane >> 4);
            uint32_t addr = sb + (uint32_t)(ks >> 2) * 16384 + r * 128 + ((seg ^ (r & 7)) << 4);
            ldsm4(qfr[ks][0], qfr[ks][1], qfr[ks][2], qfr[ks][3], addr);
        }
    }

    float oacc[16][4] = {};
    float m0 = -1e30f, m1 = -1e30f, l0 = 0.f, l1 = 0.f;

    for (int j = 0; j < 16; j++) {
        const int buf = j & 1;
        if (j + 1 < 16) {
            load_tile(sb + KOFF + (buf ^ 1) * 32768, Kh + (size_t)(j + 1) * 128 * DD);
            load_tile(sb + VOFF + (buf ^ 1) * 32768, Vh + (size_t)(j + 1) * 128 * DD);
            cp_commit(); cp_wait1();
        } else cp_wait0();
        __syncthreads();

        float sacc[16][4] = {};
        const uint32_t tK = sb + KOFF + buf * 32768;
        #pragma unroll
        for (int ks = 0; ks < 8; ks++) {
            #pragma unroll
            for (int g = 0; g < 8; g++) {
                int r = g * 16 + (lane & 7) + ((lane >> 4) << 3);
                int seg = (ks & 3) * 2 + ((lane >> 3) & 1);
                uint32_t addr = tK + (uint32_t)(ks >> 2) * 16384 + r * 128 + ((seg ^ (r & 7)) << 4);
                uint32_t b0, b1, b2, b3;
                ldsm4(b0, b1, b2, b3, addr);
                mma16816(sacc[2 * g],     qfr[ks], b0, b1);
                mma16816(sacc[2 * g + 1], qfr[ks], b2, b3);
            }
        }

        float tm0 = -1e30f, tm1 = -1e30f;
        #pragma unroll
        for (int t = 0; t < 16; t++) {
            tm0 = fmaxf(tm0, fmaxf(sacc[t][0], sacc[t][1]));
            tm1 = fmaxf(tm1, fmaxf(sacc[t][2], sacc[t][3]));
        }
        tm0 = fmaxf(tm0, __shfl_xor_sync(~0u, tm0, 1));
        tm0 = fmaxf(tm0, __shfl_xor_sync(~0u, tm0, 2));
        tm1 = fmaxf(tm1, __shfl_xor_sync(~0u, tm1, 1));
        tm1 = fmaxf(tm1, __shfl_xor_sync(~0u, tm1, 2));
        float nm0 = fmaxf(m0, tm0), nm1 = fmaxf(m1, tm1);
        float f0 = exp2f((m0 - nm0) * LOG2E), f1 = exp2f((m1 - nm1) * LOG2E);
        m0 = nm0; m1 = nm1;

        uint32_t pP[8][4];
        float rs0 = 0.f, rs1 = 0.f;
        #pragma unroll
        for (int t = 0; t < 8; t++) {
            float p00 = exp2f((sacc[2*t][0]   - nm0) * LOG2E);
            float p01 = exp2f((sacc[2*t][1]   - nm0) * LOG2E);
            float p02 = exp2f((sacc[2*t][2]   - nm1) * LOG2E);
            float p03 = exp2f((sacc[2*t][3]   - nm1) * LOG2E);
            float p10 = exp2f((sacc[2*t+1][0] - nm0) * LOG2E);
            float p11 = exp2f((sacc[2*t+1][1] - nm0) * LOG2E);
            float p12 = exp2f((sacc[2*t+1][2] - nm1) * LOG2E);
            float p13 = exp2f((sacc[2*t+1][3] - nm1) * LOG2E);
            rs0 += p00 + p01 + p10 + p11;
            rs1 += p02 + p03 + p12 + p13;
            __half2 h;
            h = __floats2half2_rn(p00, p01); pP[t][0] = *(uint32_t*)&h;
            h = __floats2half2_rn(p02, p03); pP[t][1] = *(uint32_t*)&h;
            h = __floats2half2_rn(p10, p11); pP[t][2] = *(uint32_t*)&h;
            h = __floats2half2_rn(p12, p13); pP[t][3] = *(uint32_t*)&h;
        }
        rs0 += __shfl_xor_sync(~0u, rs0, 1); rs0 += __shfl_xor_sync(~0u, rs0, 2);
        rs1 += __shfl_xor_sync(~0u, rs1, 1); rs1 += __shfl_xor_sync(~0u, rs1, 2);
        l0 = l0 * f0 + rs0; l1 = l1 * f1 + rs1;
        #pragma unroll
        for (int t = 0; t < 16; t++) {
            oacc[t][0] *= f0; oacc[t][1] *= f0;
            oacc[t][2] *= f1; oacc[t][3] *= f1;
        }

        const uint32_t tV = sb + VOFF + buf * 32768;
        #pragma unroll
        for (int t = 0; t < 8; t++) {
            #pragma unroll
            for (int g = 0; g < 8; g++) {
                int r = t * 16 + (lane & 7) + (lane & 8);
                int seg = (g & 3) * 2 + (lane >> 4);
                uint32_t addr = tV + (uint32_t)(g >> 2) * 16384 + r * 128 + ((seg ^ (r & 7)) << 4);
                uint32_t b0, b1, b2, b3;
                ldsm4t(b0, b1, b2, b3, addr);
                mma16816(oacc[2 * g],     pP[t], b0, b1);
                mma16816(oacc[2 * g + 1], pP[t], b2, b3);
            }
        }
        __syncthreads();
    }

    float inv0 = 1.f / l0, inv1 = 1.f / l1;
    size_t m = (size_t)qb * 128 + wid * 16 + (lane >> 2);
    size_t col0 = (size_t)head * 128 + (lane & 3) * 2;
    #pragma unroll
    for (int t = 0; t < 16; t++) {
        __half2 h0 = __floats2half2_rn(oacc[t][0] * inv0, oacc[t][1] * inv0);
        __half2 h1 = __floats2half2_rn(oacc[t][2] * inv1, oacc[t][3] * inv1);
        *(__half2*)&O[m * NN2 + col0 + t * 8]       = h0;
        *(__half2*)&O[(m + 8) * NN2 + col0 + t * 8] = h1;
    }
}

// ---------------- vectorized fp32 -> fp16 cast (same layout) ----------------
__global__ void cast_half(const float* __restrict__ in, __half* __restrict__ o, size_t n8) {
    size_t i = (size_t)blockIdx.x * 256 + threadIdx.x;
    if (i >= n8) return;
    float4 a = *(const float4*)&in[i * 8];
    float4 b = *(const float4*)&in[i * 8 + 4];
    __half2 h[4] = { __floats2half2_rn(a.x, a.y), __floats2half2_rn(a.z, a.w),
                     __floats2half2_rn(b.x, b.y), __floats2half2_rn(b.z, b.w) };
    *(uint2*)&o[i * 8]     = make_uint2(*(uint32_t*)&h[0], *(uint32_t*)&h[1]);
    *(uint2*)&o[i * 8 + 4] = make_uint2(*(uint32_t*)&h[2], *(uint32_t*)&h[3]);
}

// ---------------- mod partials = silu(vec) @ mod_w  (k-split) ----------------
__global__ void mod_gemv(const float* __restrict__ vec,
                         const float* __restrict__ mod_w) {
    __shared__ float sv[HID / MSPLIT];
    int tid = threadIdx.x;
    int ks = blockIdx.y;
    int k0 = ks * (HID / MSPLIT);
    for (int i = tid; i < HID / MSPLIT; i += blockDim.x) {
        float a = vec[k0 + i];
        sv[i] = a / (1.f + __expf(-a));
    }
    __syncthreads();
    int j = blockIdx.x * blockDim.x + tid;
    float acc = 0.f;
    #pragma unroll 4
    for (int k = 0; k < HID / MSPLIT; k++)
        acc += sv[k] * mod_w[(size_t)(k0 + k) * (3 * HID) + j];
    g_modp[ks][j] = acc;
}

// ---------------- layernorm + modulation -> fp16 (mod folded from partials) ----------------
__global__ void ln_mod_kernel(const float* __restrict__ x,
                              const float* __restrict__ gamma,
                              const float* __restrict__ beta,
                              const float* __restrict__ mod_b) {
    __shared__ float red[32];
    int l = blockIdx.x;
    const float* xr = x + (size_t)l * HID;
    float s = 0.f, s2 = 0.f;
    for (int i = threadIdx.x; i < HID; i += 256) {
        float v = xr[i];
        s += v; s2 += v * v;
    }
    int lane = threadIdx.x & 31, wid = threadIdx.x >> 5;
    #pragma unroll
    for (int o = 16; o; o >>= 1) { s += __shfl_down_sync(~0u, s, o); s2 += __shfl_down_sync(~0u, s2, o); }
    if (lane == 0) { red[wid] = s; red[wid + 8] = s2; }
    __syncthreads();
    float ts = 0.f, ts2 = 0.f;
    if (threadIdx.x < 8) { ts = red[threadIdx.x]; ts2 = red[threadIdx.x + 8]; }
    #pragma unroll
    for (int o = 4; o; o >>= 1) { ts += __shfl_down_sync(0xff, ts, o); ts2 += __shfl_down_sync(0xff, ts2, o); }
    if (threadIdx.x == 0) { red[0] = ts; red[1] = ts2; }
    __syncthreads();
    float mu = red[0] / HID;
    float var = red[1] / HID - mu * mu;
    float rsig = rsqrtf(var + EPSF);
    for (int i = threadIdx.x; i < HID; i += 256) {
        float shift = mod_b[i], scale = mod_b[HID + i];
        #pragma unroll
        for (int k = 0; k < MSPLIT; k++) {
            shift += g_modp[k][i];
            scale += g_modp[k][HID + i];
        }
        float lnv = (xr[i] - mu) * rsig * gamma[i] + beta[i];
        float v = (1.f + scale) * lnv + shift;
        g_xf[(size_t)l * HID + i] = __float2half_rn(v);
    }
}

// ---------------- rmsnorm + rope (q,k): warp per (which, head), lane owns 4 elems ----------------
__global__ void __launch_bounds__(256) qkv_prep(const float* __restrict__ pe,
                                                const float* __restrict__ q_scale,
                                                const float* __restrict__ k_scale) {
    const int l = blockIdx.x;
    const int grp = blockIdx.y * 8 + (threadIdx.x >> 5);  // 0..47
    const int which = grp / HH, head = grp % HH;
    const int lane = threadIdx.x & 31;
    const int d0 = lane * 4;

    // load 4 halves
    const size_t base = (size_t)l * QK2 + (size_t)which * HID + (size_t)head * DD + d0;
    uint2 raw = *(const uint2*)&g_hqk[base];
    __half2 h01 = *(__half2*)&raw.x, h23 = *(__half2*)&raw.y;
    float t0 = __half2float(__low2half(h01)),  t1 = __half2float(__high2half(h01));
    float t2 = __half2float(__low2half(h23)),  t3 = __half2float(__high2half(h23));

    // warp rmsnorm
    float ss = t0 * t0 + t1 * t1 + t2 * t2 + t3 * t3;
    #pragma unroll
    for (int o = 16; o; o >>= 1) ss += __shfl_xor_sync(~0u, ss, o);
    float r = rsqrtf(ss / DD + EPSF);

    const float* sc = which ? k_scale : q_scale;
    float s0 = t0 * r * sc[d0], s1 = t1 * r * sc[d0 + 1];
    float s2 = t2 * r * sc[d0 + 2], s3 = t3 * r * sc[d0 + 3];

    // rope: two pairs (d0,d0+1) and (d0+2,d0+3); pe row = l, pair index i = d0/2
    const float* pr = pe + ((size_t)l * (DD / 2) + (d0 >> 1)) * 4;
    float4 pa = *(const float4*)pr;        // pair i:   [j0: x,y][j1: z,w]
    float4 pb = *(const float4*)(pr + 4);  // pair i+1
    float o0 = pa.x * s0 + pa.y * s1;
    float o1 = pa.z * s0 + pa.w * s1;
    float o2 = pb.x * s2 + pb.y * s3;
    float o3 = pb.z * s2 + pb.w * s3;
    if (which == 0) {
        o0 *= 0.08838834764831845f; o1 *= 0.08838834764831845f;
        o2 *= 0.08838834764831845f; o3 *= 0.08838834764831845f;
    }
    __half2 w0 = __floats2half2_rn(o0, o1), w1 = __floats2half2_rn(o2, o3);
    const size_t oi = ((size_t)head * LL + l) * DD + d0;
    __half* dst = which ? g_kf : g_qf;
    *(uint2*)&dst[oi] = make_uint2(*(uint32_t*)&w0, *(uint32_t*)&w1);
}

// ---------------- launcher ----------------
extern "C" void kernel_launch(void* const* d_in, const int* in_sizes, int n_in,
                              void* d_out, int out_size) {
    const float* x       = (const float*)d_in[0];
    const float* vec     = (const float*)d_in[1];
    const float* pe      = (const float*)d_in[2];
    const float* mod_w   = (const float*)d_in[3];
    const float* mod_b   = (const float*)d_in[4];
    const float* gamma   = (const float*)d_in[5];
    const float* beta    = (const float*)d_in[6];
    const float* w1      = (const float*)d_in[7];
    const float* b1      = (const float*)d_in[8];
    const float* q_scale = (const float*)d_in[9];
    const float* k_scale = (const float*)d_in[10];
    const float* w2      = (const float*)d_in[11];
    const float* b2      = (const float*)d_in[12];
    float* out = (float*)d_out;

    float *p_part;
    __half *p_xf, *p_w1f, *p_hq, *p_qf, *p_kf, *p_vf, *p_ocf, *p_w2f;
    cudaGetSymbolAddress((void**)&p_part, g_part);
    cudaGetSymbolAddress((void**)&p_xf, g_xf);
    cudaGetSymbolAddress((void**)&p_w1f, g_w1f);
    cudaGetSymbolAddress((void**)&p_hq, g_hqk);
    cudaGetSymbolAddress((void**)&p_qf, g_qf);
    cudaGetSymbolAddress((void**)&p_kf, g_kf);
    cudaGetSymbolAddress((void**)&p_vf, g_vf);
    cudaGetSymbolAddress((void**)&p_ocf, g_ocf);
    cudaGetSymbolAddress((void**)&p_w2f, g_w2f);

    const int SMEM = 2 * (256 + 128) * 256;   // 196608
    const int FSMEM = 163840;
    cudaFuncSetAttribute((const void*)hgemm<0>, cudaFuncAttributeMaxDynamicSharedMemorySize, SMEM);
    cudaFuncSetAttribute((const void*)hgemm<6>, cudaFuncAttributeMaxDynamicSharedMemorySize, SMEM);
    cudaFuncSetAttribute((const void*)flash_attn, cudaFuncAttributeMaxDynamicSharedMemorySize, FSMEM);

    // lazy-init side stream + events (handles only; captured graph identical every call)
    static cudaStream_t s1 = nullptr;
    static cudaEvent_t e_fork = nullptr, e_w1 = nullptr, e_w2 = nullptr;
    if (!s1) {
        cudaStreamCreate(&s1);
        cudaEventCreateWithFlags(&e_fork, cudaEventDisableTiming);
        cudaEventCreateWithFlags(&e_w1, cudaEventDisableTiming);
        cudaEventCreateWithFlags(&e_w2, cudaEventDisableTiming);
    }

    // fork side stream into capture
    cudaEventRecord(e_fork, 0);
    cudaStreamWaitEvent(s1, e_fork, 0);

    // side stream: weight casts
    cast_half<<<(unsigned)(((size_t)HID * NN1 / 8 + 255) / 256), 256, 0, s1>>>(w1, p_w1f, (size_t)HID * NN1 / 8);
    cudaEventRecord(e_w1, s1);
    cast_half<<<(unsigned)(((size_t)NN2 * HID / 8 + 255) / 256), 256, 0, s1>>>(w2, p_w2f, (size_t)NN2 * HID / 8);
    cudaEventRecord(e_w2, s1);

    // main stream
    mod_gemv<<<dim3((3 * HID) / 256, MSPLIT), 256>>>(vec, mod_w);
    ln_mod_kernel<<<LL, 256>>>(x, gamma, beta, mod_b);

    cudaStreamWaitEvent(0, e_w1, 0);
    // gemm1: q,k -> fp16 g_hqk; v -> g_vf; mlp -> gelu -> g_ocf (all fused)
    hgemm<6><<<dim3(LL / 256, NN1 / 128, 1), 512, SMEM>>>(
        p_xf, HID, 0, p_w1f, NN1, 0,
        nullptr, 0, 0, HID, b1, p_ocf, NN2, p_vf, p_hq);
    qkv_prep<<<dim3(LL, 6), 256>>>(pe, q_scale, k_scale);
    flash_attn<<<dim3(LL / 128, HH), 256, FSMEM>>>(p_qf, p_kf, p_vf, p_ocf);

    cudaStreamWaitEvent(0, e_w2, 0);
    // gemm2 split-K=3: partials = oc @ w2
    hgemm<0><<<dim3(LL / 256, HID / 128, KSPLIT), 512, SMEM>>>(
        p_ocf, NN2, KCHUNK, p_w2f, HID, (long)KCHUNK * HID,
        p_part, HID, (long)LL * HID, KCHUNK, nullptr, nullptr, 0, nullptr, nullptr);
    reduce_out<<<((size_t)LL * HID / 4) / 256, 256>>>(x, b2, mod_b, out);
}

// round 16
// speedup vs baseline: 1.0425x; 1.0072x over previous
#include <cuda_runtime.h>
#include <cuda_fp16.h>
#include <math.h>
#include <stdint.h>

// Problem constants
#define LL   2048
#define HH   24
#define DD   128
#define HID  3072
#define MLPD 12288
#define NN1  21504   // 3*HID + MLP
#define NN2  15360   // HID + MLP
#define QKV  9216    // 3*HID
#define QK2  6144    // 2*HID
#define EPSF 1e-6f
#define LOG2E 1.4426950408889634f
#define KSPLIT 3
#define KCHUNK (NN2 / KSPLIT)   // 5120
#define MSPLIT 4                // mod_gemv k-split

// ---------------- scratch (static device arrays; no allocs) ----------------
__device__ float g_mod[3 * HID];
__device__ float g_modp[MSPLIT][3 * HID];
__device__ __half g_xf[(size_t)LL * HID];              // x_mod fp16
__device__ __half g_w1f[(size_t)HID * NN1];            // w1 fp16 [K][N]
__device__ __half g_hqk[(size_t)LL * QK2];             // gemm1 q|k out fp16
__device__ __half g_qf[(size_t)HH * LL * DD];          // q (pre-scaled by D^-0.5)
__device__ __half g_kf[(size_t)HH * LL * DD];
__device__ __half g_vf[(size_t)HH * LL * DD];          // v fp16 [h][l][d]
__device__ __half g_ocf[(size_t)LL * NN2];             // attn | gelu(mlp) fp16
__device__ __half g_w2f[(size_t)NN2 * HID];            // w2 fp16 [K][N]
__device__ float  g_part[(size_t)KSPLIT * LL * HID];   // split-K partials

// ---------------- helpers ----------------
__device__ __forceinline__ uint32_t smem_u32(const void* p) {
    uint32_t a;
    asm("{ .reg .u64 t; cvta.to.shared.u64 t, %1; cvt.u32.u64 %0, t; }" : "=r"(a) : "l"(p));
    return a;
}
__device__ __forceinline__ void cpasync16(uint32_t dst, const void* src) {
    asm volatile("cp.async.cg.shared.global [%0], [%1], 16;" :: "r"(dst), "l"(src));
}
__device__ __forceinline__ void cp_commit() { asm volatile("cp.async.commit_group;"); }
__device__ __forceinline__ void cp_wait1()  { asm volatile("cp.async.wait_group 1;" ::: "memory"); }
__device__ __forceinline__ void cp_wait0()  { asm volatile("cp.async.wait_group 0;" ::: "memory"); }

__device__ __forceinline__ void ldsm4(uint32_t& r0, uint32_t& r1, uint32_t& r2, uint32_t& r3, uint32_t a) {
    asm volatile("ldmatrix.sync.aligned.m8n8.x4.shared.b16 {%0,%1,%2,%3}, [%4];"
                 : "=r"(r0), "=r"(r1), "=r"(r2), "=r"(r3) : "r"(a));
}
__device__ __forceinline__ void ldsm4t(uint32_t& r0, uint32_t& r1, uint32_t& r2, uint32_t& r3, uint32_t a) {
    asm volatile("ldmatrix.sync.aligned.m8n8.x4.trans.shared.b16 {%0,%1,%2,%3}, [%4];"
                 : "=r"(r0), "=r"(r1), "=r"(r2), "=r"(r3) : "r"(a));
}
__device__ __forceinline__ void mma16816(float* c, const uint32_t* a, uint32_t b0, uint32_t b1) {
    asm volatile(
        "mma.sync.aligned.m16n8k16.row.col.f32.f16.f16.f32 "
        "{%0,%1,%2,%3},{%4,%5,%6,%7},{%8,%9},{%0,%1,%2,%3};\n"
        : "+f"(c[0]), "+f"(c[1]), "+f"(c[2]), "+f"(c[3])
        : "r"(a[0]), "r"(a[1]), "r"(a[2]), "r"(a[3]), "r"(b0), "r"(b1));
}
__device__ __forceinline__ float gelu_f(float v) {
    float c = 0.7978845608028654f * (v + 0.044715f * v * v * v);
    return 0.5f * v * (1.f + tanhf(c));
}

// ---------------- fp16 HMMA GEMM ----------------
// A [M][K] row-major fp16; B [K][N] (k-major) fp16 via ldmatrix.trans.
// CTA tile 256(m) x 128(n), 512 threads = 16 warps (4m x 4n, warp tile 64x32).
// K-chunk 128, double-buffered cp.async, swizzled smem.
// EPI: 0 plain fp32 | 6 gemm1 mixed: n<QK2 -> +bias fp16 Hqk; [QK2,QKV) -> +bias fp16 V; >=QKV -> gelu(+bias) fp16 C2
template<int EPI>
__global__ void __launch_bounds__(512, 1) hgemm(
    const __half* __restrict__ A, size_t lda, long sA,
    const __half* __restrict__ B, size_t ldb, long sB,
    float* __restrict__ C, size_t ldc, long sC, int K,
    const float* __restrict__ bias,
    __half* __restrict__ C2, size_t ldc2,
    __half* __restrict__ V, __half* __restrict__ Hqk)
{
    extern __shared__ char smem[];
    constexpr int TILEA = 256 * 256;     // 64 KB
    constexpr int TILEB = 128 * 256;     // 32 KB
    constexpr int STAGE = TILEA + TILEB; // 96 KB
    const uint32_t sb = smem_u32(smem);
    const int tid = threadIdx.x, wid = tid >> 5, lane = tid & 31;
    const int wm = wid & 3, wn = wid >> 2;    // 4m x 4n

    A += (long)blockIdx.z * sA;
    B += (long)blockIdx.z * sB;
    C += (long)blockIdx.z * sC;

    const size_t row0 = (size_t)blockIdx.x * 256;
    const size_t col0 = (size_t)blockIdx.y * 128;
    const __half* baseA = A + row0 * lda;
    const __half* baseB = B + col0;          // [K][N]: advance rows by k

    auto load_stage = [&](int s) {
        const uint32_t st = sb + (uint32_t)(s & 1) * STAGE;
        const int ko = s * 128;
        #pragma unroll
        for (int j = 0; j < 8; j++) {
            int c = tid + j * 512;
            int row = c >> 4, seg = c & 15;
            uint32_t dst = st + row * 256 + ((seg ^ (row & 7)) << 4);
            cpasync16(dst, (const char*)(baseA + ko + (size_t)row * lda) + seg * 16);
        }
        #pragma unroll
        for (int j = 0; j < 4; j++) {
            int c = tid + j * 512;
            int row = c >> 4, seg = c & 15;
            uint32_t dst = st + TILEA + row * 256 + ((seg ^ (row & 7)) << 4);
            cpasync16(dst, (const char*)(baseB + (size_t)(ko + row) * ldb) + seg * 16);
        }
    };

    float acc[4][4][4] = {};
    const int S = K >> 7;

    load_stage(0); cp_commit();
    for (int s = 0; s < S; s++) {
        cp_wait0();
        __syncthreads();
        if (s + 1 < S) { load_stage(s + 1); cp_commit(); }

        const uint32_t st = sb + (uint32_t)(s & 1) * STAGE;
        const uint32_t tA = st, tB = st + TILEA;

        #pragma unroll
        for (int kg = 0; kg < 8; kg++) {
            uint32_t af[4][4];
            {
                int arow = wm * 64 + (lane & 15);
                int ak8 = kg * 2 + (lane >> 4);
                #pragma unroll
                for (int im = 0; im < 4; im++) {
                    int r = arow + im * 16;
                    uint32_t off = r * 256 + ((ak8 ^ (r & 7)) << 4);
                    ldsm4(af[im][0], af[im][1], af[im][2], af[im][3], tA + off);
                }
            }
            int brow = kg * 16 + (lane & 7) + (lane & 8);
            #pragma unroll
            for (int g = 0; g < 2; g++) {
                int seg = wn * 4 + g * 2 + (lane >> 4);
                uint32_t off = brow * 256 + ((seg ^ (brow & 7)) << 4);
                uint32_t b0, b1, b2, b3;
                ldsm4t(b0, b1, b2, b3, tB + off);
                #pragma unroll
                for (int im = 0; im < 4; im++) {
                    mma16816(acc[im][2 * g],     af[im], b0, b1);
                    mma16816(acc[im][2 * g + 1], af[im], b2, b3);
                }
            }
        }
    }

    const int mode = (EPI == 6) ? ((col0 >= QKV) ? 2 : (col0 >= QK2 ? 1 : 0)) : 3;
    #pragma unroll
    for (int im = 0; im < 4; im++) {
        #pragma unroll
        for (int in = 0; in < 4; in++) {
            size_t m0 = row0 + wm * 64 + im * 16 + (lane >> 2);
            size_t n  = col0 + wn * 32 + in * 8 + (lane & 3) * 2;
            #pragma unroll
            for (int half = 0; half < 2; half++) {
                size_t m = m0 + half * 8;
                float v0 = acc[im][in][half * 2 + 0];
                float v1 = acc[im][in][half * 2 + 1];
                if (mode == 3) {
                    *(float2*)&C[m * ldc + n] = make_float2(v0, v1);
                } else if (mode == 0) {
                    v0 += bias[n]; v1 += bias[n + 1];
                    *(__half2*)&Hqk[m * QK2 + n] = __floats2half2_rn(v0, v1);
                } else if (mode == 1) {
                    v0 += bias[n]; v1 += bias[n + 1];
                    size_t head = (n - QK2) >> 7, d = (n - QK2) & 127;
                    *(__half2*)&V[(head * LL + m) * DD + d] = __floats2half2_rn(v0, v1);
                } else {
                    v0 += bias[n]; v1 += bias[n + 1];
                    __half2 h = __floats2half2_rn(gelu_f(v0), gelu_f(v1));
                    *(__half2*)&C2[m * ldc2 + (n - QK2)] = h;
                }
            }
        }
    }
}

// ---------------- split-K reduce: out = x + gate*(p0+p1+p2+b2) ----------------
__global__ void reduce_out(const float* __restrict__ x, const float* __restrict__ b2,
                           float* __restrict__ out) {
    size_t i = ((size_t)blockIdx.x * 256 + threadIdx.x) * 4;
    int n = (int)(i % HID);
    const size_t STR = (size_t)LL * HID;
    float4 p0 = *(const float4*)&g_part[i];
    float4 p1 = *(const float4*)&g_part[STR + i];
    float4 p2 = *(const float4*)&g_part[2 * STR + i];
    float4 xb = *(const float4*)&x[i];
    float4 bb = *(const float4*)&b2[n];
    float4 gg = *(const float4*)&g_mod[2 * HID + n];
    float4 o;
    o.x = xb.x + gg.x * (p0.x + p1.x + p2.x + bb.x);
    o.y = xb.y + gg.y * (p0.y + p1.y + p2.y + bb.y);
    o.z = xb.z + gg.z * (p0.z + p1.z + p2.z + bb.z);
    o.w = xb.w + gg.w * (p0.w + p1.w + p2.w + bb.w);
    *(float4*)&out[i] = o;
}

// ---------------- fused flash attention ----------------
__global__ void __launch_bounds__(256, 1) flash_attn(
    const __half* __restrict__ Qg, const __half* __restrict__ Kg,
    const __half* __restrict__ Vg, __half* __restrict__ O)
{
    extern __shared__ char smem[];
    const uint32_t sb = smem_u32(smem);
    const int tid = threadIdx.x, wid = tid >> 5, lane = tid & 31;
    const int qb = blockIdx.x, head = blockIdx.y;
    constexpr uint32_t KOFF = 32768, VOFF = 98304;

    const __half* Qh = Qg + ((size_t)head * LL + (size_t)qb * 128) * DD;
    const __half* Kh = Kg + (size_t)head * LL * DD;
    const __half* Vh = Vg + (size_t)head * LL * DD;

    auto load_tile = [&](uint32_t dst, const __half* g) {
        #pragma unroll
        for (int i = 0; i < 8; i++) {
            int c = tid + i * 256;
            int row = c >> 4, ds = c & 15;
            uint32_t off = (uint32_t)(ds >> 3) * 16384 + row * 128 + (((ds & 7) ^ (row & 7)) << 4);
            cpasync16(dst + off, (const char*)g + (size_t)row * 256 + ds * 16);
        }
    };

    load_tile(sb, Qh); cp_commit();
    load_tile(sb + KOFF, Kh); load_tile(sb + VOFF, Vh); cp_commit();
    cp_wait1();
    __syncthreads();

    uint32_t qfr[8][4];
    {
        int r = wid * 16 + (lane & 15);
        #pragma unroll
        for (int ks = 0; ks < 8; ks++) {
            int seg = (ks & 3) * 2 + (lane >> 4);
            uint32_t addr = sb + (uint32_t)(ks >> 2) * 16384 + r * 128 + ((seg ^ (r & 7)) << 4);
            ldsm4(qfr[ks][0], qfr[ks][1], qfr[ks][2], qfr[ks][3], addr);
        }
    }

    float oacc[16][4] = {};
    float m0 = -1e30f, m1 = -1e30f, l0 = 0.f, l1 = 0.f;

    for (int j = 0; j < 16; j++) {
        const int buf = j & 1;
        if (j + 1 < 16) {
            load_tile(sb + KOFF + (buf ^ 1) * 32768, Kh + (size_t)(j + 1) * 128 * DD);
            load_tile(sb + VOFF + (buf ^ 1) * 32768, Vh + (size_t)(j + 1) * 128 * DD);
            cp_commit(); cp_wait1();
        } else cp_wait0();
        __syncthreads();

        float sacc[16][4] = {};
        const uint32_t tK = sb + KOFF + buf * 32768;
        #pragma unroll
        for (int ks = 0; ks < 8; ks++) {
            #pragma unroll
            for (int g = 0; g < 8; g++) {
                int r = g * 16 + (lane & 7) + ((lane >> 4) << 3);
                int seg = (ks & 3) * 2 + ((lane >> 3) & 1);
                uint32_t addr = tK + (uint32_t)(ks >> 2) * 16384 + r * 128 + ((seg ^ (r & 7)) << 4);
                uint32_t b0, b1, b2, b3;
                ldsm4(b0, b1, b2, b3, addr);
                mma16816(sacc[2 * g],     qfr[ks], b0, b1);
                mma16816(sacc[2 * g + 1], qfr[ks], b2, b3);
            }
        }

        float tm0 = -1e30f, tm1 = -1e30f;
        #pragma unroll
        for (int t = 0; t < 16; t++) {
            tm0 = fmaxf(tm0, fmaxf(sacc[t][0], sacc[t][1]));
            tm1 = fmaxf(tm1, fmaxf(sacc[t][2], sacc[t][3]));
        }
        tm0 = fmaxf(tm0, __shfl_xor_sync(~0u, tm0, 1));
        tm0 = fmaxf(tm0, __shfl_xor_sync(~0u, tm0, 2));
        tm1 = fmaxf(tm1, __shfl_xor_sync(~0u, tm1, 1));
        tm1 = fmaxf(tm1, __shfl_xor_sync(~0u, tm1, 2));
        float nm0 = fmaxf(m0, tm0), nm1 = fmaxf(m1, tm1);
        float f0 = exp2f((m0 - nm0) * LOG2E), f1 = exp2f((m1 - nm1) * LOG2E);
        m0 = nm0; m1 = nm1;

        uint32_t pP[8][4];
        float rs0 = 0.f, rs1 = 0.f;
        #pragma unroll
        for (int t = 0; t < 8; t++) {
            float p00 = exp2f((sacc[2*t][0]   - nm0) * LOG2E);
            float p01 = exp2f((sacc[2*t][1]   - nm0) * LOG2E);
            float p02 = exp2f((sacc[2*t][2]   - nm1) * LOG2E);
            float p03 = exp2f((sacc[2*t][3]   - nm1) * LOG2E);
            float p10 = exp2f((sacc[2*t+1][0] - nm0) * LOG2E);
            float p11 = exp2f((sacc[2*t+1][1] - nm0) * LOG2E);
            float p12 = exp2f((sacc[2*t+1][2] - nm1) * LOG2E);
            float p13 = exp2f((sacc[2*t+1][3] - nm1) * LOG2E);
            rs0 += p00 + p01 + p10 + p11;
            rs1 += p02 + p03 + p12 + p13;
            __half2 h;
            h = __floats2half2_rn(p00, p01); pP[t][0] = *(uint32_t*)&h;
            h = __floats2half2_rn(p02, p03); pP[t][1] = *(uint32_t*)&h;
            h = __floats2half2_rn(p10, p11); pP[t][2] = *(uint32_t*)&h;
            h = __floats2half2_rn(p12, p13); pP[t][3] = *(uint32_t*)&h;
        }
        rs0 += __shfl_xor_sync(~0u, rs0, 1); rs0 += __shfl_xor_sync(~0u, rs0, 2);
        rs1 += __shfl_xor_sync(~0u, rs1, 1); rs1 += __shfl_xor_sync(~0u, rs1, 2);
        l0 = l0 * f0 + rs0; l1 = l1 * f1 + rs1;
        #pragma unroll
        for (int t = 0; t < 16; t++) {
            oacc[t][0] *= f0; oacc[t][1] *= f0;
            oacc[t][2] *= f1; oacc[t][3] *= f1;
        }

        const uint32_t tV = sb + VOFF + buf * 32768;
        #pragma unroll
        for (int t = 0; t < 8; t++) {
            #pragma unroll
            for (int g = 0; g < 8; g++) {
                int r = t * 16 + (lane & 7) + (lane & 8);
                int seg = (g & 3) * 2 + (lane >> 4);
                uint32_t addr = tV + (uint32_t)(g >> 2) * 16384 + r * 128 + ((seg ^ (r & 7)) << 4);
                uint32_t b0, b1, b2, b3;
                ldsm4t(b0, b1, b2, b3, addr);
                mma16816(oacc[2 * g],     pP[t], b0, b1);
                mma16816(oacc[2 * g + 1], pP[t], b2, b3);
            }
        }
        __syncthreads();
    }

    float inv0 = 1.f / l0, inv1 = 1.f / l1;
    size_t m = (size_t)qb * 128 + wid * 16 + (lane >> 2);
    size_t col0 = (size_t)head * 128 + (lane & 3) * 2;
    #pragma unroll
    for (int t = 0; t < 16; t++) {
        __half2 h0 = __floats2half2_rn(oacc[t][0] * inv0, oacc[t][1] * inv0);
        __half2 h1 = __floats2half2_rn(oacc[t][2] * inv1, oacc[t][3] * inv1);
        *(__half2*)&O[m * NN2 + col0 + t * 8]       = h0;
        *(__half2*)&O[(m + 8) * NN2 + col0 + t * 8] = h1;
    }
}

// ---------------- vectorized fp32 -> fp16 cast (same layout) ----------------
__global__ void cast_half(const float* __restrict__ in, __half* __restrict__ o, size_t n8) {
    size_t i = (size_t)blockIdx.x * 256 + threadIdx.x;
    if (i >= n8) return;
    float4 a = *(const float4*)&in[i * 8];
    float4 b = *(const float4*)&in[i * 8 + 4];
    __half2 h[4] = { __floats2half2_rn(a.x, a.y), __floats2half2_rn(a.z, a.w),
                     __floats2half2_rn(b.x, b.y), __floats2half2_rn(b.z, b.w) };
    *(uint2*)&o[i * 8]     = make_uint2(*(uint32_t*)&h[0], *(uint32_t*)&h[1]);
    *(uint2*)&o[i * 8 + 4] = make_uint2(*(uint32_t*)&h[2], *(uint32_t*)&h[3]);
}

// ---------------- mod partials = silu(vec) @ mod_w  (k-split) ----------------
__global__ void mod_gemv(const float* __restrict__ vec,
                         const float* __restrict__ mod_w) {
    __shared__ float sv[HID / MSPLIT];
    int tid = threadIdx.x;
    int ks = blockIdx.y;
    int k0 = ks * (HID / MSPLIT);
    for (int i = tid; i < HID / MSPLIT; i += blockDim.x) {
        float a = vec[k0 + i];
        sv[i] = a / (1.f + __expf(-a));
    }
    __syncthreads();
    int j = blockIdx.x * blockDim.x + tid;
    float acc = 0.f;
    #pragma unroll 4
    for (int k = 0; k < HID / MSPLIT; k++)
        acc += sv[k] * mod_w[(size_t)(k0 + k) * (3 * HID) + j];
    g_modp[ks][j] = acc;
}
__global__ void mod_reduce(const float* __restrict__ mod_b) {
    int j = blockIdx.x * 256 + threadIdx.x;
    float s = mod_b[j];
    #pragma unroll
    for (int k = 0; k < MSPLIT; k++) s += g_modp[k][j];
    g_mod[j] = s;
}

// ---------------- layernorm + modulation -> fp16 ----------------
__global__ void ln_mod_kernel(const float* __restrict__ x,
                              const float* __restrict__ gamma,
                              const float* __restrict__ beta) {
    __shared__ float red[32];
    int l = blockIdx.x;
    const float* xr = x + (size_t)l * HID;
    float s = 0.f, s2 = 0.f;
    for (int i = threadIdx.x; i < HID; i += 256) {
        float v = xr[i];
        s += v; s2 += v * v;
    }
    int lane = threadIdx.x & 31, wid = threadIdx.x >> 5;
    #pragma unroll
    for (int o = 16; o; o >>= 1) { s += __shfl_down_sync(~0u, s, o); s2 += __shfl_down_sync(~0u, s2, o); }
    if (lane == 0) { red[wid] = s; red[wid + 8] = s2; }
    __syncthreads();
    float ts = 0.f, ts2 = 0.f;
    if (threadIdx.x < 8) { ts = red[threadIdx.x]; ts2 = red[threadIdx.x + 8]; }
    #pragma unroll
    for (int o = 4; o; o >>= 1) { ts += __shfl_down_sync(0xff, ts, o); ts2 += __shfl_down_sync(0xff, ts2, o); }
    if (threadIdx.x == 0) { red[0] = ts; red[1] = ts2; }
    __syncthreads();
    float mu = red[0] / HID;
    float var = red[1] / HID - mu * mu;
    float rsig = rsqrtf(var + EPSF);
    for (int i = threadIdx.x; i < HID; i += 256) {
        float lnv = (xr[i] - mu) * rsig * gamma[i] + beta[i];
        float v = (1.f + g_mod[HID + i]) * lnv + g_mod[i];
        g_xf[(size_t)l * HID + i] = __float2half_rn(v);
    }
}

// ---------------- rmsnorm + rope (q,k): warp per (which, head), lane owns 4 elems ----------------
__global__ void __launch_bounds__(256) qkv_prep(const float* __restrict__ pe,
                                                const float* __restrict__ q_scale,
                                                const float* __restrict__ k_scale) {
    const int l = blockIdx.x;
    const int grp = blockIdx.y * 8 + (threadIdx.x >> 5);  // 0..47
    const int which = grp / HH, head = grp % HH;
    const int lane = threadIdx.x & 31;
    const int d0 = lane * 4;

    const size_t base = (size_t)l * QK2 + (size_t)which * HID + (size_t)head * DD + d0;
    uint2 raw = *(const uint2*)&g_hqk[base];
    __half2 h01 = *(__half2*)&raw.x, h23 = *(__half2*)&raw.y;
    float t0 = __half2float(__low2half(h01)),  t1 = __half2float(__high2half(h01));
    float t2 = __half2float(__low2half(h23)),  t3 = __half2float(__high2half(h23));

    float ss = t0 * t0 + t1 * t1 + t2 * t2 + t3 * t3;
    #pragma unroll
    for (int o = 16; o; o >>= 1) ss += __shfl_xor_sync(~0u, ss, o);
    float r = rsqrtf(ss / DD + EPSF);

    const float* sc = which ? k_scale : q_scale;
    float s0 = t0 * r * sc[d0], s1 = t1 * r * sc[d0 + 1];
    float s2 = t2 * r * sc[d0 + 2], s3 = t3 * r * sc[d0 + 3];

    const float* pr = pe + ((size_t)l * (DD / 2) + (d0 >> 1)) * 4;
    float4 pa = *(const float4*)pr;
    float4 pb = *(const float4*)(pr + 4);
    float o0 = pa.x * s0 + pa.y * s1;
    float o1 = pa.z * s0 + pa.w * s1;
    float o2 = pb.x * s2 + pb.y * s3;
    float o3 = pb.z * s2 + pb.w * s3;
    if (which == 0) {
        o0 *= 0.08838834764831845f; o1 *= 0.08838834764831845f;
        o2 *= 0.08838834764831845f; o3 *= 0.08838834764831845f;
    }
    __half2 w0 = __floats2half2_rn(o0, o1), w1 = __floats2half2_rn(o2, o3);
    const size_t oi = ((size_t)head * LL + l) * DD + d0;
    __half* dst = which ? g_kf : g_qf;
    *(uint2*)&dst[oi] = make_uint2(*(uint32_t*)&w0, *(uint32_t*)&w1);
}

// ---------------- launcher ----------------
extern "C" void kernel_launch(void* const* d_in, const int* in_sizes, int n_in,
                              void* d_out, int out_size) {
    const float* x       = (const float*)d_in[0];
    const float* vec     = (const float*)d_in[1];
    const float* pe      = (const float*)d_in[2];
    const float* mod_w   = (const float*)d_in[3];
    const float* mod_b   = (const float*)d_in[4];
    const float* gamma   = (const float*)d_in[5];
    const float* beta    = (const float*)d_in[6];
    const float* w1      = (const float*)d_in[7];
    const float* b1      = (const float*)d_in[8];
    const float* q_scale = (const float*)d_in[9];
    const float* k_scale = (const float*)d_in[10];
    const float* w2      = (const float*)d_in[11];
    const float* b2      = (const float*)d_in[12];
    float* out = (float*)d_out;

    float *p_part;
    __half *p_xf, *p_w1f, *p_hq, *p_qf, *p_kf, *p_vf, *p_ocf, *p_w2f;
    cudaGetSymbolAddress((void**)&p_part, g_part);
    cudaGetSymbolAddress((void**)&p_xf, g_xf);
    cudaGetSymbolAddress((void**)&p_w1f, g_w1f);
    cudaGetSymbolAddress((void**)&p_hq, g_hqk);
    cudaGetSymbolAddress((void**)&p_qf, g_qf);
    cudaGetSymbolAddress((void**)&p_kf, g_kf);
    cudaGetSymbolAddress((void**)&p_vf, g_vf);
    cudaGetSymbolAddress((void**)&p_ocf, g_ocf);
    cudaGetSymbolAddress((void**)&p_w2f, g_w2f);

    const int SMEM = 2 * (256 + 128) * 256;   // 196608
    const int FSMEM = 163840;
    cudaFuncSetAttribute((const void*)hgemm<0>, cudaFuncAttributeMaxDynamicSharedMemorySize, SMEM);
    cudaFuncSetAttribute((const void*)hgemm<6>, cudaFuncAttributeMaxDynamicSharedMemorySize, SMEM);
    cudaFuncSetAttribute((const void*)flash_attn, cudaFuncAttributeMaxDynamicSharedMemorySize, FSMEM);

    // lazy-init side stream + events (handles only; captured graph identical every call)
    static cudaStream_t s1 = nullptr;
    static cudaEvent_t e_fork = nullptr, e_w1 = nullptr, e_w2 = nullptr;
    if (!s1) {
        cudaStreamCreate(&s1);
        cudaEventCreateWithFlags(&e_fork, cudaEventDisableTiming);
        cudaEventCreateWithFlags(&e_w1, cudaEventDisableTiming);
        cudaEventCreateWithFlags(&e_w2, cudaEventDisableTiming);
    }

    // fork side stream into capture
    cudaEventRecord(e_fork, 0);
    cudaStreamWaitEvent(s1, e_fork, 0);

    // side stream: weight casts
    cast_half<<<(unsigned)(((size_t)HID * NN1 / 8 + 255) / 256), 256, 0, s1>>>(w1, p_w1f, (size_t)HID * NN1 / 8);
    cudaEventRecord(e_w1, s1);
    cast_half<<<(unsigned)(((size_t)NN2 * HID / 8 + 255) / 256), 256, 0, s1>>>(w2, p_w2f, (size_t)NN2 * HID / 8);
    cudaEventRecord(e_w2, s1);

    // main stream
    mod_gemv<<<dim3((3 * HID) / 256, MSPLIT), 256>>>(vec, mod_w);
    mod_reduce<<<(3 * HID) / 256, 256>>>(mod_b);
    ln_mod_kernel<<<LL, 256>>>(x, gamma, beta);

    cudaStreamWaitEvent(0, e_w1, 0);
    // gemm1: q,k -> fp16 g_hqk; v -> g_vf; mlp -> gelu -> g_ocf (all fused)
    hgemm<6><<<dim3(LL / 256, NN1 / 128, 1), 512, SMEM>>>(
        p_xf, HID, 0, p_w1f, NN1, 0,
        nullptr, 0, 0, HID, b1, p_ocf, NN2, p_vf, p_hq);
    qkv_prep<<<dim3(LL, 6), 256>>>(pe, q_scale, k_scale);
    flash_attn<<<dim3(LL / 128, HH), 256, FSMEM>>>(p_qf, p_kf, p_vf, p_ocf);

    cudaStreamWaitEvent(0, e_w2, 0);
    // gemm2 split-K=3: partials = oc @ w2
    hgemm<0><<<dim3(LL / 256, HID / 128, KSPLIT), 512, SMEM>>>(
        p_ocf, NN2, KCHUNK, p_w2f, HID, (long)KCHUNK * HID,
        p_part, HID, (long)LL * HID, KCHUNK, nullptr, nullptr, 0, nullptr, nullptr);
    reduce_out<<<((size_t)LL * HID / 4) / 256, 256>>>(x, b2, out);
}